// round 7
// baseline (speedup 1.0000x reference)
#include <cuda_runtime.h>
#include <math.h>

// Problem dims (fixed by the dataset)
#define Bsz 512
#define Tt  32
#define Hh  768
#define Ff  3072
#define Ee  3

// ---------------------------------------------------------------------------
// Device-global scratch (no cudaMalloc allowed).
//   g_h  : intermediate gelu activations, (B*T, F) fp32  (~201 MB)
//   g_sel/g_gate : routing results per batch
// Declared as float4 to guarantee 16B alignment for vectorized access.
// ---------------------------------------------------------------------------
__device__ float4 g_h4[(size_t)Bsz * Tt * Ff / 4];
__device__ int    g_sel[Bsz];
__device__ float  g_gate[Bsz];

// ---------------------------------------------------------------------------
// Kernel 1: routing.  scores[b,e] = softmax_e( (1/T) * sum_{t,h} x[b,t,h]*Wg[e,h] )
// sel = argmax (first index on tie, matching jax top_k), gate = softmax value.
// One block per batch, 256 threads.
// ---------------------------------------------------------------------------
__global__ __launch_bounds__(256) void route_kernel(const float* __restrict__ x,
                                                    const float* __restrict__ Wg)
{
    __shared__ float sWg[Ee * Hh];
    __shared__ float red[Ee][256];
    const int b   = blockIdx.x;
    const int tid = threadIdx.x;

    for (int i = tid; i < Ee * Hh; i += 256) sWg[i] = Wg[i];
    __syncthreads();

    const float* X = x + (size_t)b * Tt * Hh;
    float a0 = 0.f, a1 = 0.f, a2 = 0.f;
    for (int i = tid; i < Tt * Hh; i += 256) {
        float xv = X[i];
        int h = i % Hh;
        a0 += xv * sWg[h];
        a1 += xv * sWg[Hh + h];
        a2 += xv * sWg[2 * Hh + h];
    }
    red[0][tid] = a0; red[1][tid] = a1; red[2][tid] = a2;
    __syncthreads();
    for (int off = 128; off > 0; off >>= 1) {
        if (tid < off) {
            red[0][tid] += red[0][tid + off];
            red[1][tid] += red[1][tid + off];
            red[2][tid] += red[2][tid + off];
        }
        __syncthreads();
    }
    if (tid == 0) {
        const float inv_t = 1.0f / (float)Tt;
        float s0 = red[0][0] * inv_t;
        float s1 = red[1][0] * inv_t;
        float s2 = red[2][0] * inv_t;
        int   sel = 0;
        float m   = s0;
        if (s1 > m) { m = s1; sel = 1; }
        if (s2 > m) { m = s2; sel = 2; }
        float e0 = expf(s0 - m), e1 = expf(s1 - m), e2 = expf(s2 - m);
        // softmax value at the argmax: exp(0) / sum
        g_sel[b]  = sel;
        g_gate[b] = 1.0f / (e0 + e1 + e2);
    }
}

// exact (erf-based) gelu, matching jax.nn.gelu(approximate=False)
__device__ __forceinline__ float gelu_exact(float v)
{
    return 0.5f * v * (1.0f + erff(v * 0.70710678118654752440f));
}

// packed fp32x2 fma (Blackwell FFMA2 — only reachable via PTX)
__device__ __forceinline__ unsigned long long fma2(unsigned long long a,
                                                   unsigned long long b,
                                                   unsigned long long c)
{
    unsigned long long d;
    asm("fma.rn.f32x2 %0, %1, %2, %3;" : "=l"(d) : "l"(a), "l"(b), "l"(c));
    return d;
}

union Q4 { float4 q; unsigned long long u[2]; };

// ---------------------------------------------------------------------------
// Kernel 2/3: per-batch expert GEMM.
//   MODE 0 (GEMM1): Y = gelu(X @ W1[e] + b1[e]),  X = x[b] (32 x K=768),  N = F
//                   writes g_h
//   MODE 1 (GEMM2): Y = gate * (X @ W2[e] + b2[e]), X = g_h[b] (32 x K=3072), N = H
//                   writes d_out
// Tile: M=32 (full batch), Ntile=256, Kc=16.  256 threads, 4 rows x 8 cols each.
// All fp32 math; inner product uses packed f32x2 FMA.
// ---------------------------------------------------------------------------
template <int K, int N, int MODE>
__global__ __launch_bounds__(256) void mlp_gemm(const float* __restrict__ Xall,
                                                const float* __restrict__ Wall,
                                                const float* __restrict__ bias,
                                                float* __restrict__ Yall)
{
    __shared__ float Xs[32 * 16];        // 2 KB
    __shared__ float Ws[16 * 256];       // 16 KB

    const int b   = blockIdx.y;
    const int n0  = blockIdx.x * 256;
    const int tid = threadIdx.x;
    const int tx  = tid & 31;
    const int ty  = tid >> 5;
    const int r0  = ty * 4;

    const int e = g_sel[b];
    const float* X = (MODE == 0) ? (Xall + (size_t)b * Tt * K)
                                 : (reinterpret_cast<const float*>(g_h4) + (size_t)b * Tt * K);
    const float* W  = Wall + (size_t)e * K * N;
    const float* Bv = bias + (size_t)e * N;
    float* Y = (MODE == 0) ? (reinterpret_cast<float*>(g_h4) + (size_t)b * Tt * N)
                           : (Yall + (size_t)b * Tt * N);

    unsigned long long acc[4][4];
#pragma unroll
    for (int i = 0; i < 4; i++)
#pragma unroll
        for (int j = 0; j < 4; j++) acc[i][j] = 0ull;

    for (int k0 = 0; k0 < K; k0 += 16) {
        // ---- load X tile: 32 rows x 16 k, float2 per thread ----
        {
            int row = tid >> 3;
            int kk  = (tid & 7) << 1;
            float2 v = *reinterpret_cast<const float2*>(X + (size_t)row * K + k0 + kk);
            Xs[row * 16 + kk]     = v.x;
            Xs[row * 16 + kk + 1] = v.y;
        }
        // ---- load W tile: 16 k x 256 n, 4x float4 per thread (coalesced) ----
#pragma unroll
        for (int j = 0; j < 4; j++) {
            int f4 = tid + j * 256;          // 0..1023 float4 slots
            int kk = f4 >> 6;                // 64 float4 per row
            int c4 = f4 & 63;
            float4 v = *reinterpret_cast<const float4*>(W + (size_t)(k0 + kk) * N + n0 + (c4 << 2));
            *reinterpret_cast<float4*>(&Ws[kk * 256 + (c4 << 2)]) = v;
        }
        __syncthreads();

#pragma unroll
        for (int kk = 0; kk < 16; kk++) {
            unsigned long long A[4];
#pragma unroll
            for (int i = 0; i < 4; i++) {
                float a = Xs[(r0 + i) * 16 + kk];          // broadcast read
                asm("mov.b64 %0, {%1, %1};" : "=l"(A[i]) : "f"(a));
            }
            Q4 wlo, whi;                                    // LDS.128, conflict-free
            wlo.q = *reinterpret_cast<const float4*>(&Ws[kk * 256 + (tx << 2)]);
            whi.q = *reinterpret_cast<const float4*>(&Ws[kk * 256 + 128 + (tx << 2)]);
#pragma unroll
            for (int i = 0; i < 4; i++) {
                acc[i][0] = fma2(A[i], wlo.u[0], acc[i][0]);
                acc[i][1] = fma2(A[i], wlo.u[1], acc[i][1]);
                acc[i][2] = fma2(A[i], whi.u[0], acc[i][2]);
                acc[i][3] = fma2(A[i], whi.u[1], acc[i][3]);
            }
        }
        __syncthreads();
    }

    // ---- epilogue ----
    const int cL = n0 + (tx << 2);
    const int cH = cL + 128;
    float4 bL = *reinterpret_cast<const float4*>(Bv + cL);
    float4 bH = *reinterpret_cast<const float4*>(Bv + cH);
    float g = (MODE == 1) ? g_gate[b] : 1.0f;

#pragma unroll
    for (int i = 0; i < 4; i++) {
        float v[8];
        asm("mov.b64 {%0, %1}, %2;" : "=f"(v[0]), "=f"(v[1]) : "l"(acc[i][0]));
        asm("mov.b64 {%0, %1}, %2;" : "=f"(v[2]), "=f"(v[3]) : "l"(acc[i][1]));
        asm("mov.b64 {%0, %1}, %2;" : "=f"(v[4]), "=f"(v[5]) : "l"(acc[i][2]));
        asm("mov.b64 {%0, %1}, %2;" : "=f"(v[6]), "=f"(v[7]) : "l"(acc[i][3]));
        v[0] += bL.x; v[1] += bL.y; v[2] += bL.z; v[3] += bL.w;
        v[4] += bH.x; v[5] += bH.y; v[6] += bH.z; v[7] += bH.w;
        if (MODE == 0) {
#pragma unroll
            for (int j = 0; j < 8; j++) v[j] = gelu_exact(v[j]);
        } else {
#pragma unroll
            for (int j = 0; j < 8; j++) v[j] *= g;
        }
        float* Yrow = Y + (size_t)(r0 + i) * N;
        float4 o0 = make_float4(v[0], v[1], v[2], v[3]);
        float4 o1 = make_float4(v[4], v[5], v[6], v[7]);
        *reinterpret_cast<float4*>(Yrow + cL) = o0;
        *reinterpret_cast<float4*>(Yrow + cH) = o1;
    }
}

// ---------------------------------------------------------------------------
// Launcher: route -> GEMM1(gelu) -> GEMM2(gate). All on default stream,
// graph-capturable, no allocations.
// Inputs (metadata order): x, Wg, W1, b1, W2, b2 (all float32).
// ---------------------------------------------------------------------------
extern "C" void kernel_launch(void* const* d_in, const int* in_sizes, int n_in,
                              void* d_out, int out_size)
{
    const float* x  = (const float*)d_in[0];
    const float* Wg = (const float*)d_in[1];
    const float* W1 = (const float*)d_in[2];
    const float* b1 = (const float*)d_in[3];
    const float* W2 = (const float*)d_in[4];
    const float* b2 = (const float*)d_in[5];
    float* out = (float*)d_out;

    route_kernel<<<Bsz, 256>>>(x, Wg);

    // GEMM1: (32 x 768) @ (768 x 3072) per batch, gelu epilogue -> g_h
    mlp_gemm<Hh, Ff, 0><<<dim3(Ff / 256, Bsz), 256>>>(x, W1, b1, nullptr);

    // GEMM2: (32 x 3072) @ (3072 x 768) per batch, gate epilogue -> out
    mlp_gemm<Ff, Hh, 1><<<dim3(Hh / 256, Bsz), 256>>>(nullptr, W2, b2, out);
}